// round 15
// baseline (speedup 1.0000x reference)
#include <cuda_runtime.h>
#include <cuda_bf16.h>
#include <cstddef>

#define NB     4
#define CIN    256
#define CDIM   512
#define HIN    56
#define NNF    3136      // 56*56
#define PQ     784       // 28*28
#define NHEADS 8
#define HD     64
#define SCALE  0.125f
#define NTILES 49        // 3136/64

// ---------------- scratch layout (single __device__ array, float units) ----------------
#define SZ_MAP  1605632ull     // 4*512*784
#define SZ_TQ   802816ull      // 4*256*784
#define SZ_KV   6422528ull     // 4*512*3136
#define SZ_ATTH 39337984ull    // 4*8*784*3136 bf16 -> half the floats
#define SZ_PS   1229312ull     // 4*784*8*49
#define SZ_LI   25088ull       // 4*784*8

#define OFF_XPROJ 0ull
#define OFF_TQ    (OFF_XPROJ + SZ_MAP)
#define OFF_Q     (OFF_TQ    + SZ_TQ)
#define OFF_QN    (OFF_Q     + SZ_MAP)
#define OFF_K     (OFF_QN    + SZ_MAP)
#define OFF_V     (OFF_K     + SZ_KV)
#define OFF_VLOC  (OFF_V     + SZ_KV)
#define OFF_O1    (OFF_VLOC  + SZ_MAP)
#define OFF_O2    (OFF_O1    + SZ_MAP)
#define OFF_S1    (OFF_O2    + SZ_MAP)
#define OFF_A2    (OFF_S1    + SZ_ATTH)
#define OFF_PS    (OFF_A2    + SZ_ATTH)
#define OFF_LI    (OFF_PS    + SZ_PS)
#define SCRATCH_TOTAL (OFF_LI + SZ_LI)

__device__ float g_scratch[SCRATCH_TOTAL];

// ---------------- packed f32x2 helpers ----------------
__device__ __forceinline__ void ffma2(float2& acc, const float2 a, const float2 b) {
    asm("fma.rn.f32x2 %0, %1, %2, %0;"
        : "+l"(reinterpret_cast<unsigned long long&>(acc))
        : "l"(reinterpret_cast<const unsigned long long&>(a)),
          "l"(reinterpret_cast<const unsigned long long&>(b)));
}
__device__ __forceinline__ float2 dup2(float v) {
    float2 r;
    asm("mov.b64 %0, {%1, %1};"
        : "=l"(reinterpret_cast<unsigned long long&>(r)) : "f"(v));
    return r;
}

// =================== unified GEMM: 64m x 64p tile, 128 threads ===================
// Y[b][m][p] = sum_k A[m][k]*X[b][k][p] (+bias), optional hardswish on X.
// thread tile: 4m x 8p.  Requires P % 8 == 0.
__global__ __launch_bounds__(128)
void gemm64(const float* __restrict__ A, const float* __restrict__ X,
            const float* __restrict__ bias, float* __restrict__ Y,
            int M, int K, int P, int hsw)
{
    __shared__ __align__(16) float As[16 * 68];
    __shared__ __align__(16) float Xs[16 * 68];
    int b  = blockIdx.z;
    int m0 = blockIdx.y * 64;
    int p0 = blockIdx.x * 64;
    int t  = threadIdx.x;
    int ty = t >> 3, tx = t & 7;     // ty: 0..15 (m-group), tx: 0..7 (p-group of 8)

    float2 acc[4][4];
#pragma unroll
    for (int i = 0; i < 4; i++)
#pragma unroll
        for (int j = 0; j < 4; j++) acc[i][j] = make_float2(0.f, 0.f);

    for (int k0 = 0; k0 < K; k0 += 16) {
#pragma unroll
        for (int it = 0; it < 8; it++) {
            int idx = t + it * 128;
            int m = idx >> 4, k = idx & 15;
            As[k * 68 + m] = A[(size_t)(m0 + m) * K + k0 + k];
        }
#pragma unroll
        for (int it = 0; it < 2; it++) {
            int u = t + it * 128;
            int kk = u >> 4, pg = u & 15;
            int p = p0 + pg * 4;
            float4 v = make_float4(0.f, 0.f, 0.f, 0.f);
            if (p < P) v = *(const float4*)&X[((size_t)b * K + k0 + kk) * P + p];
            if (hsw) {
                float c;
                c = fminf(fmaxf(v.x + 3.f, 0.f), 6.f); v.x = v.x * c * (1.f / 6.f);
                c = fminf(fmaxf(v.y + 3.f, 0.f), 6.f); v.y = v.y * c * (1.f / 6.f);
                c = fminf(fmaxf(v.z + 3.f, 0.f), 6.f); v.z = v.z * c * (1.f / 6.f);
                c = fminf(fmaxf(v.w + 3.f, 0.f), 6.f); v.w = v.w * c * (1.f / 6.f);
            }
            *(float4*)&Xs[kk * 68 + pg * 4] = v;
        }
        __syncthreads();
#pragma unroll
        for (int kk = 0; kk < 16; kk++) {
            float2 am[4];
#pragma unroll
            for (int i = 0; i < 4; i++) am[i] = dup2(As[kk * 68 + ty * 4 + i]);
            float4 x0 = *(const float4*)&Xs[kk * 68 + tx * 8];
            float4 x1 = *(const float4*)&Xs[kk * 68 + tx * 8 + 4];
            float2 xp[4] = { make_float2(x0.x, x0.y), make_float2(x0.z, x0.w),
                             make_float2(x1.x, x1.y), make_float2(x1.z, x1.w) };
#pragma unroll
            for (int i = 0; i < 4; i++)
#pragma unroll
                for (int j = 0; j < 4; j++) ffma2(acc[i][j], am[i], xp[j]);
        }
        __syncthreads();
    }
    int pbase = p0 + tx * 8;
    if (pbase < P) {
#pragma unroll
        for (int i = 0; i < 4; i++) {
            int m = m0 + ty * 4 + i;
            float bv = bias ? bias[m] : 0.f;
            float* yb = Y + ((size_t)b * M + m) * P + pbase;
            float4 w0 = make_float4(acc[i][0].x + bv, acc[i][0].y + bv,
                                    acc[i][1].x + bv, acc[i][1].y + bv);
            float4 w1 = make_float4(acc[i][2].x + bv, acc[i][2].y + bv,
                                    acc[i][3].x + bv, acc[i][3].y + bv);
            *(float4*)yb = w0;
            *(float4*)(yb + 4) = w1;
        }
    }
}

// =================== 3x3 s2 pad1 conv (implicit GEMM, 64m x 64p, 128 thr) ===================
__global__ __launch_bounds__(128)
void conv3x3_kernel(const float* __restrict__ X, const float* __restrict__ W,
                    const float* __restrict__ bias, float* __restrict__ Y,
                    int CinPG, int CinTot, int CoutPG, int Cout)
{
    __shared__ __align__(16) float As[16 * 68];
    __shared__ __align__(16) float Xs[16 * 68];
    int b  = blockIdx.z;
    int m0 = blockIdx.y * 64;
    int p0 = blockIdx.x * 64;
    int g  = m0 / CoutPG;
    int K  = CinPG * 9;
    int t  = threadIdx.x;
    int ty = t >> 3, tx = t & 7;

    const float* Xb = X + (size_t)(b * CinTot + g * CinPG) * NNF;

    float2 acc[4][4];
#pragma unroll
    for (int i = 0; i < 4; i++)
#pragma unroll
        for (int j = 0; j < 4; j++) acc[i][j] = make_float2(0.f, 0.f);

    for (int k0 = 0; k0 < K; k0 += 16) {
#pragma unroll
        for (int it = 0; it < 8; it++) {
            int idx = t + it * 128;
            int m = idx >> 4, k = idx & 15;
            As[k * 68 + m] = W[(size_t)(m0 + m) * K + k0 + k];
        }
#pragma unroll
        for (int it = 0; it < 8; it++) {
            int u = t + it * 128;
            int kk = u >> 6, pp = u & 63;
            int k = k0 + kk;
            int ci = k / 9, r9 = k - ci * 9;
            int ky = r9 / 3, kx = r9 - ky * 3;
            int p = p0 + pp;
            float v = 0.f;
            if (p < PQ) {
                int py = p / 28, px = p - py * 28;
                int iy = 2 * py - 1 + ky, ix = 2 * px - 1 + kx;
                if ((unsigned)iy < (unsigned)HIN && (unsigned)ix < (unsigned)HIN)
                    v = Xb[(size_t)ci * NNF + iy * HIN + ix];
            }
            Xs[kk * 68 + pp] = v;
        }
        __syncthreads();
#pragma unroll
        for (int kk = 0; kk < 16; kk++) {
            float2 am[4];
#pragma unroll
            for (int i = 0; i < 4; i++) am[i] = dup2(As[kk * 68 + ty * 4 + i]);
            float4 x0 = *(const float4*)&Xs[kk * 68 + tx * 8];
            float4 x1 = *(const float4*)&Xs[kk * 68 + tx * 8 + 4];
            float2 xp[4] = { make_float2(x0.x, x0.y), make_float2(x0.z, x0.w),
                             make_float2(x1.x, x1.y), make_float2(x1.z, x1.w) };
#pragma unroll
            for (int i = 0; i < 4; i++)
#pragma unroll
                for (int j = 0; j < 4; j++) ffma2(acc[i][j], am[i], xp[j]);
        }
        __syncthreads();
    }
    int pbase = p0 + tx * 8;
    if (pbase < PQ) {
#pragma unroll
        for (int i = 0; i < 4; i++) {
            int m = m0 + ty * 4 + i;
            float bv = bias ? bias[m] : 0.f;
            float* yb = Y + ((size_t)b * Cout + m) * PQ + pbase;
            float4 w0 = make_float4(acc[i][0].x + bv, acc[i][0].y + bv,
                                    acc[i][1].x + bv, acc[i][1].y + bv);
            float4 w1 = make_float4(acc[i][2].x + bv, acc[i][2].y + bv,
                                    acc[i][3].x + bv, acc[i][3].y + bv);
            *(float4*)yb = w0;
            *(float4*)(yb + 4) = w1;
        }
    }
}

// ---------------- GroupNorm ----------------
__global__ __launch_bounds__(256)
void gn_kernel(float* __restrict__ data, const float* __restrict__ w,
               const float* __restrict__ bgn, int HW,
               const float* __restrict__ addsrc, float* __restrict__ dst)
{
    __shared__ float rs[256], rss[256];
    __shared__ float sstat[2];
    int grp = blockIdx.x, b = blockIdx.y;
    int t = threadIdx.x;
    size_t base = ((size_t)b * CDIM + grp * 16) * HW;
    int n = 16 * HW;
    float s = 0.f, ss = 0.f;
    for (int e = t; e < n; e += 256) {
        float v = data[base + e];
        s += v; ss += v * v;
    }
    rs[t] = s; rss[t] = ss;
    __syncthreads();
    for (int o = 128; o > 0; o >>= 1) {
        if (t < o) { rs[t] += rs[t + o]; rss[t] += rss[t + o]; }
        __syncthreads();
    }
    if (t == 0) {
        float mean = rs[0] / (float)n;
        float var  = rss[0] / (float)n - mean * mean;
        sstat[0] = mean;
        sstat[1] = rsqrtf(var + 1e-5f);
    }
    __syncthreads();
    float mean = sstat[0], rstd = sstat[1];
    float* out = dst ? dst : data;
    for (int e = t; e < n; e += 256) {
        int c = grp * 16 + e / HW;
        float v = (data[base + e] - mean) * rstd * w[c] + bgn[c];
        if (addsrc) v += addsrc[base + e];
        out[base + e] = v;
    }
}

// ---------------- depthwise 3x3 s2 conv + bias + stride-2 pool add ----------------
__global__ __launch_bounds__(256)
void dwpool_kernel(const float* __restrict__ x, const float* __restrict__ w,
                   const float* __restrict__ bias, float* __restrict__ tq)
{
    int idx = blockIdx.x * 256 + threadIdx.x;
    if (idx >= NB * CIN * PQ) return;
    int p = idx % PQ;
    int c = (idx / PQ) % CIN;
    int b = idx / (PQ * CIN);
    int py = p / 28, px = p - py * 28;
    const float* xb = x + ((size_t)b * CIN + c) * NNF;
    float acc = bias[c] + xb[(2 * py) * HIN + 2 * px];
#pragma unroll
    for (int ky = 0; ky < 3; ky++) {
        int iy = 2 * py - 1 + ky;
        if ((unsigned)iy >= (unsigned)HIN) continue;
#pragma unroll
        for (int kx = 0; kx < 3; kx++) {
            int ix = 2 * px - 1 + kx;
            if ((unsigned)ix >= (unsigned)HIN) continue;
            acc += w[c * 9 + ky * 3 + kx] * xb[iy * HIN + ix];
        }
    }
    tq[idx] = acc;
}

// ---------------- head-axis l2 norm for K (in place) ----------------
__global__ __launch_bounds__(256)
void hn_k_kernel(float* __restrict__ k)
{
    int idx = blockIdx.x * 256 + threadIdx.x;
    if (idx >= NB * HD * NNF) return;
    int nidx = idx % NNF;
    int d = (idx / NNF) % HD;
    int b = idx / (NNF * HD);
    float v[NHEADS];
    float s = 0.f;
#pragma unroll
    for (int h = 0; h < NHEADS; h++) {
        v[h] = k[((size_t)b * CDIM + h * HD + d) * NNF + nidx];
        s += v[h] * v[h];
    }
    float inv = 1.f / fmaxf(sqrtf(s), 1e-12f);
#pragma unroll
    for (int h = 0; h < NHEADS; h++)
        k[((size_t)b * CDIM + h * HD + d) * NNF + nidx] = v[h] * inv;
}

// ---------------- head-axis l2 norm for Q + transpose to [b][p][c] ----------------
__global__ __launch_bounds__(256)
void hn_q_kernel(const float* __restrict__ q, float* __restrict__ qn)
{
    int idx = blockIdx.x * 256 + threadIdx.x;
    if (idx >= NB * HD * PQ) return;
    int p = idx % PQ;
    int d = (idx / PQ) % HD;
    int b = idx / (PQ * HD);
    float v[NHEADS];
    float s = 0.f;
#pragma unroll
    for (int h = 0; h < NHEADS; h++) {
        v[h] = q[((size_t)b * CDIM + h * HD + d) * PQ + p];
        s += v[h] * v[h];
    }
    float inv = 1.f / fmaxf(sqrtf(s), 1e-12f);
#pragma unroll
    for (int h = 0; h < NHEADS; h++)
        qn[((size_t)b * PQ + p) * CDIM + h * HD + d] = v[h] * inv;
}

// =================== attention: exp(th1-mixed scores) -> bf16 + partial sums ===================
// block: 32q x 64n tile, 128 threads, thread-tile 4q x 4n.
__global__ __launch_bounds__(128)
void attn_s1_kernel(const float* __restrict__ qn, const float* __restrict__ kn,
                    const float* __restrict__ th1, const float* __restrict__ ab,
                    const int* __restrict__ bidx, __nv_bfloat16* __restrict__ s1,
                    float* __restrict__ partial)
{
    __shared__ __align__(16) float qs[32 * 68];
    __shared__ __align__(16) float ks[64 * 68];
    __shared__ float2 th1s[64];
    int b  = blockIdx.z;
    int q0 = blockIdx.y * 32;
    int n0 = blockIdx.x * 64;
    int t  = threadIdx.x;
    int qy = t >> 4, tx = t & 15;

    if (t < 64) { float w = th1[t]; th1s[t] = make_float2(w, w); }

    int4 bi[4];
#pragma unroll
    for (int j = 0; j < 4; j++) {
        int q = q0 + qy * 4 + j;
        bi[j] = (q < PQ) ? *(const int4*)&bidx[(size_t)q * NNF + n0 + tx * 4]
                         : make_int4(0, 0, 0, 0);
    }

    float2 acc[NHEADS][4][2];
#pragma unroll
    for (int o = 0; o < NHEADS; o++)
#pragma unroll
        for (int j = 0; j < 4; j++) {
            acc[o][j][0] = make_float2(0.f, 0.f);
            acc[o][j][1] = make_float2(0.f, 0.f);
        }

    for (int i = 0; i < NHEADS; i++) {
        __syncthreads();
#pragma unroll
        for (int it = 0; it < 4; it++) {
            int u = t + it * 128;
            int qq = u >> 4, dg = u & 15;
            int q = q0 + qq;
            float4 v = make_float4(0.f, 0.f, 0.f, 0.f);
            if (q < PQ) v = *(const float4*)&qn[((size_t)b * PQ + q) * CDIM + i * HD + dg * 4];
            *(float4*)&qs[qq * 68 + dg * 4] = v;
        }
#pragma unroll
        for (int it = 0; it < 8; it++) {
            int u = t + it * 128;
            int dd = u >> 4, ng = u & 15;
            float4 v = *(const float4*)&kn[((size_t)b * CDIM + i * HD + dd) * NNF + n0 + ng * 4];
            *(float4*)&ks[dd * 68 + ng * 4] = v;
        }
        __syncthreads();

        float2 s[4][2];
#pragma unroll
        for (int j = 0; j < 4; j++) { s[j][0] = make_float2(0.f, 0.f); s[j][1] = make_float2(0.f, 0.f); }

#pragma unroll 8
        for (int d = 0; d < HD; d++) {
            float4 k4 = *(const float4*)&ks[d * 68 + tx * 4];
            float2 k01 = make_float2(k4.x, k4.y);
            float2 k23 = make_float2(k4.z, k4.w);
#pragma unroll
            for (int j = 0; j < 4; j++) {
                float2 qp = dup2(qs[(qy * 4 + j) * 68 + d]);
                ffma2(s[j][0], qp, k01);
                ffma2(s[j][1], qp, k23);
            }
        }
        const float* abr = ab + (size_t)i * NNF;
        float2 w[NHEADS];
#pragma unroll
        for (int o = 0; o < NHEADS; o++) w[o] = th1s[o * 8 + i];
#pragma unroll
        for (int j = 0; j < 4; j++) {
            float2 t01 = make_float2(s[j][0].x * SCALE + abr[bi[j].x],
                                     s[j][0].y * SCALE + abr[bi[j].y]);
            float2 t23 = make_float2(s[j][1].x * SCALE + abr[bi[j].z],
                                     s[j][1].y * SCALE + abr[bi[j].w]);
#pragma unroll
            for (int o = 0; o < NHEADS; o++) {
                ffma2(acc[o][j][0], w[o], t01);
                ffma2(acc[o][j][1], w[o], t23);
            }
        }
    }

#pragma unroll
    for (int o = 0; o < NHEADS; o++) {
#pragma unroll
        for (int j = 0; j < 4; j++) {
            int q = q0 + qy * 4 + j;
            float4 ev;
            ev.x = __expf(acc[o][j][0].x);
            ev.y = __expf(acc[o][j][0].y);
            ev.z = __expf(acc[o][j][1].x);
            ev.w = __expf(acc[o][j][1].y);
            float ps = (ev.x + ev.y) + (ev.z + ev.w);
#pragma unroll
            for (int off = 8; off > 0; off >>= 1)
                ps += __shfl_xor_sync(0xffffffffu, ps, off);
            if (q < PQ) {
                __nv_bfloat162 e01 = __floats2bfloat162_rn(ev.x, ev.y);
                __nv_bfloat162 e23 = __floats2bfloat162_rn(ev.z, ev.w);
                uint2 pk;
                pk.x = *(unsigned*)&e01;
                pk.y = *(unsigned*)&e23;
                *(uint2*)&s1[(((size_t)b * NHEADS + o) * PQ + q) * NNF + n0 + tx * 4] = pk;
                if (tx == 0)
                    partial[(((size_t)b * PQ + q) * NHEADS + o) * NTILES + blockIdx.x] = ps;
            }
        }
    }
}

// ---------------- reduce partial sums -> 1/l ----------------
__global__ __launch_bounds__(256)
void reduce_l_kernel(const float* __restrict__ partial, float* __restrict__ linv)
{
    int idx = blockIdx.x * 256 + threadIdx.x;
    if (idx >= NB * PQ * NHEADS) return;
    const float* p = partial + (size_t)idx * NTILES;
    float s = 0.f;
#pragma unroll
    for (int i = 0; i < NTILES; i++) s += p[i];
    linv[idx] = 1.f / s;
}

// ---------------- normalize + th2 head-mix (bf16 streaming) ----------------
__global__ __launch_bounds__(256)
void mix_kernel(const __nv_bfloat16* __restrict__ e, const float* __restrict__ linv,
                const float* __restrict__ th2, __nv_bfloat16* __restrict__ a2)
{
    __shared__ float th2s[64];
    int q = blockIdx.x, b = blockIdx.y, t = threadIdx.x;
    if (t < 64) th2s[t] = th2[t];
    __syncthreads();
    float li[NHEADS];
#pragma unroll
    for (int o = 0; o < NHEADS; o++)
        li[o] = linv[((size_t)b * PQ + q) * NHEADS + o];
    size_t base = ((size_t)b * NHEADS * PQ + q) * NNF;
    for (int n = t * 8; n < NNF; n += 2048) {
        float p[NHEADS][8];
#pragma unroll
        for (int i = 0; i < NHEADS; i++) {
            uint4 raw = *(const uint4*)&e[base + (size_t)i * PQ * NNF + n];
            const __nv_bfloat162* h = (const __nv_bfloat162*)&raw;
#pragma unroll
            for (int g = 0; g < 4; g++) {
                float2 f = __bfloat1622float2(h[g]);
                p[i][g * 2 + 0] = f.x * li[i];
                p[i][g * 2 + 1] = f.y * li[i];
            }
        }
#pragma unroll
        for (int o = 0; o < NHEADS; o++) {
            float s[8];
#pragma unroll
            for (int g = 0; g < 8; g++) s[g] = 0.f;
#pragma unroll
            for (int i = 0; i < NHEADS; i++) {
                float w = th2s[o * 8 + i];
#pragma unroll
                for (int g = 0; g < 8; g++) s[g] += w * p[i][g];
            }
            uint4 outp;
            __nv_bfloat162* oh = (__nv_bfloat162*)&outp;
#pragma unroll
            for (int g = 0; g < 4; g++)
                oh[g] = __floats2bfloat162_rn(s[g * 2], s[g * 2 + 1]);
            *(uint4*)&a2[base + (size_t)o * PQ * NNF + n] = outp;
        }
    }
}

// =================== AV GEMM (64d x 64q tile, 128 thr) + v_local add ===================
__global__ __launch_bounds__(128)
void av_kernel(const __nv_bfloat16* __restrict__ a2, const float* __restrict__ v,
               const float* __restrict__ vloc, float* __restrict__ out)
{
    __shared__ __align__(16) float As[16 * 68];
    __shared__ __align__(16) float Xs[16 * 68];
    int b = blockIdx.z, o = blockIdx.y, p0 = blockIdx.x * 64;
    int t = threadIdx.x, ty = t >> 3, tx = t & 7;
    const float* vb = v + ((size_t)b * CDIM + o * HD) * NNF;
    const __nv_bfloat16* ab = a2 + (((size_t)b * NHEADS + o) * PQ) * NNF;

    float2 acc[4][4];
#pragma unroll
    for (int i = 0; i < 4; i++)
#pragma unroll
        for (int j = 0; j < 4; j++) acc[i][j] = make_float2(0.f, 0.f);

    for (int n0 = 0; n0 < NNF; n0 += 16) {
#pragma unroll
        for (int it = 0; it < 8; it++) {
            int idx = t + it * 128;
            int dd = idx >> 4, kk = idx & 15;
            As[kk * 68 + dd] = vb[(size_t)dd * NNF + n0 + kk];
        }
#pragma unroll
        for (int it = 0; it < 8; it++) {
            int idx = t + it * 128;
            int pp = idx >> 4, kk = idx & 15;
            int p = p0 + pp;
            Xs[kk * 68 + pp] = (p < PQ) ? __bfloat162float(ab[(size_t)p * NNF + n0 + kk]) : 0.f;
        }
        __syncthreads();
#pragma unroll
        for (int kk = 0; kk < 16; kk++) {
            float2 am[4];
#pragma unroll
            for (int i = 0; i < 4; i++) am[i] = dup2(As[kk * 68 + ty * 4 + i]);
            float4 x0 = *(const float4*)&Xs[kk * 68 + tx * 8];
            float4 x1 = *(const float4*)&Xs[kk * 68 + tx * 8 + 4];
            float2 xp[4] = { make_float2(x0.x, x0.y), make_float2(x0.z, x0.w),
                             make_float2(x1.x, x1.y), make_float2(x1.z, x1.w) };
#pragma unroll
            for (int i = 0; i < 4; i++)
#pragma unroll
                for (int j = 0; j < 4; j++) ffma2(acc[i][j], am[i], xp[j]);
        }
        __syncthreads();
    }
    int pbase = p0 + tx * 8;
    if (pbase < PQ) {
#pragma unroll
        for (int i = 0; i < 4; i++) {
            int c = o * HD + ty * 4 + i;
            const float* vl = vloc + ((size_t)b * CDIM + c) * PQ + pbase;
            float* ob = out + ((size_t)b * CDIM + c) * PQ + pbase;
            float4 w0 = make_float4(acc[i][0].x + vl[0], acc[i][0].y + vl[1],
                                    acc[i][1].x + vl[2], acc[i][1].y + vl[3]);
            float4 w1 = make_float4(acc[i][2].x + vl[4], acc[i][2].y + vl[5],
                                    acc[i][3].x + vl[6], acc[i][3].y + vl[7]);
            *(float4*)ob = w0;
            *(float4*)(ob + 4) = w1;
        }
    }
}

// ---------------- launch ----------------
extern "C" void kernel_launch(void* const* d_in, const int* in_sizes, int n_in,
                              void* d_out, int out_size)
{
    const float* x         = (const float*)d_in[0];
    const float* q_local_w = (const float*)d_in[1];
    const float* q_local_b = (const float*)d_in[2];
    const float* q_proj_w  = (const float*)d_in[3];
    const float* q_proj_b  = (const float*)d_in[4];
    const float* q_gn_w    = (const float*)d_in[5];
    const float* q_gn_b    = (const float*)d_in[6];
    const float* k_w       = (const float*)d_in[7];
    const float* k_gn_w    = (const float*)d_in[8];
    const float* k_gn_b    = (const float*)d_in[9];
    const float* v_w       = (const float*)d_in[10];
    const float* v_gn_w    = (const float*)d_in[11];
    const float* v_gn_b    = (const float*)d_in[12];
    const float* loc_w     = (const float*)d_in[13];
    const float* loc_b     = (const float*)d_in[14];
    const float* loc_gn_w  = (const float*)d_in[15];
    const float* loc_gn_b  = (const float*)d_in[16];
    const float* th1_w     = (const float*)d_in[17];
    const float* th2_w     = (const float*)d_in[18];
    const float* out_w     = (const float*)d_in[19];
    const float* out_gn_w  = (const float*)d_in[20];
    const float* out_gn_b  = (const float*)d_in[21];
    const float* proj_w    = (const float*)d_in[22];
    const float* proj_b    = (const float*)d_in[23];
    const float* proj_gn_w = (const float*)d_in[24];
    const float* proj_gn_b = (const float*)d_in[25];
    const float* attn_bias = (const float*)d_in[26];
    const int*   bias_idxs = (const int*)d_in[27];
    float* out = (float*)d_out;

    float* S = nullptr;
    cudaGetSymbolAddress((void**)&S, g_scratch);
    float* xproj = S + OFF_XPROJ;
    float* tq    = S + OFF_TQ;
    float* qbuf  = S + OFF_Q;
    float* qn    = S + OFF_QN;
    float* kbuf  = S + OFF_K;
    float* vbuf  = S + OFF_V;
    float* vloc  = S + OFF_VLOC;
    float* o1    = S + OFF_O1;
    float* o2    = S + OFF_O2;
    __nv_bfloat16* s1 = (__nv_bfloat16*)(S + OFF_S1);
    __nv_bfloat16* a2 = (__nv_bfloat16*)(S + OFF_A2);
    float* psum  = S + OFF_PS;
    float* linv  = S + OFF_LI;

    dim3 blk128(128);
    dim3 blk256(256);

    // proj path: conv3x3 s2 (256->512) + bias, then GN in place
    conv3x3_kernel<<<dim3(13, 8, NB), blk128>>>(x, proj_w, proj_b, xproj, 256, 256, 512, 512);
    gn_kernel<<<dim3(32, NB), blk256>>>(xproj, proj_gn_w, proj_gn_b, PQ, nullptr, nullptr);

    // q path
    dwpool_kernel<<<dim3((NB * CIN * PQ + 255) / 256), blk256>>>(x, q_local_w, q_local_b, tq);
    gemm64<<<dim3(13, 8, NB), blk128>>>(q_proj_w, tq, q_proj_b, qbuf, 512, 256, PQ, 0);
    gn_kernel<<<dim3(32, NB), blk256>>>(qbuf, q_gn_w, q_gn_b, PQ, nullptr, nullptr);

    // k path
    gemm64<<<dim3(49, 8, NB), blk128>>>(k_w, x, nullptr, kbuf, 512, 256, NNF, 0);
    gn_kernel<<<dim3(32, NB), blk256>>>(kbuf, k_gn_w, k_gn_b, NNF, nullptr, nullptr);
    hn_k_kernel<<<dim3((NB * HD * NNF + 255) / 256), blk256>>>(kbuf);

    // v path
    gemm64<<<dim3(49, 8, NB), blk128>>>(v_w, x, nullptr, vbuf, 512, 256, NNF, 0);
    gn_kernel<<<dim3(32, NB), blk256>>>(vbuf, v_gn_w, v_gn_b, NNF, nullptr, nullptr);

    // v_local: grouped conv3x3 s2 (8 groups of 64) + bias, GN in place
    conv3x3_kernel<<<dim3(13, 8, NB), blk128>>>(vbuf, loc_w, loc_b, vloc, 64, 512, 64, 512);
    gn_kernel<<<dim3(32, NB), blk256>>>(vloc, loc_gn_w, loc_gn_b, PQ, nullptr, nullptr);

    // q l2norm over heads + transpose
    hn_q_kernel<<<dim3((NB * HD * PQ + 255) / 256), blk256>>>(qbuf, qn);

    // attention: exp(QK*scale + bias mixed by th1) -> bf16, partial row sums
    attn_s1_kernel<<<dim3(NTILES, 25, NB), blk128>>>(qn, kbuf, th1_w, attn_bias,
                                                     bias_idxs, s1, psum);

    // row sums -> 1/l
    reduce_l_kernel<<<dim3((NB * PQ * NHEADS + 255) / 256), blk256>>>(psum, linv);

    // normalize + th2 mix (bf16 -> bf16)
    mix_kernel<<<dim3(PQ, NB), blk256>>>(s1, linv, th2_w, a2);

    // AV + v_local
    av_kernel<<<dim3(13, NHEADS, NB), blk128>>>(a2, vbuf, vloc, o1);

    // hardswish -> out 1x1 conv (512->512)
    gemm64<<<dim3(13, 8, NB), blk128>>>(out_w, o1, nullptr, o2, 512, 512, PQ, 1);

    // final GN + residual add -> d_out
    gn_kernel<<<dim3(32, NB), blk256>>>(o2, out_gn_w, out_gn_b, PQ, xproj, out);
}

// round 16
// speedup vs baseline: 1.0029x; 1.0029x over previous
#include <cuda_runtime.h>
#include <cuda_bf16.h>
#include <cstddef>

#define NB     4
#define CIN    256
#define CDIM   512
#define HIN    56
#define NNF    3136      // 56*56
#define PQ     784       // 28*28
#define NHEADS 8
#define HD     64
#define SCALE  0.125f
#define NTILES 49        // 3136/64

// ---------------- scratch layout (single __device__ array, float units) ----------------
#define SZ_MAP  1605632ull     // 4*512*784
#define SZ_TQ   802816ull      // 4*256*784
#define SZ_KV   6422528ull     // 4*512*3136
#define SZ_ATTH 39337984ull    // 4*8*784*3136 bf16 -> half the floats
#define SZ_PS   1229312ull     // 4*784*8*49
#define SZ_LI   25088ull       // 4*784*8

#define OFF_XPROJ 0ull
#define OFF_TQ    (OFF_XPROJ + SZ_MAP)
#define OFF_Q     (OFF_TQ    + SZ_TQ)
#define OFF_QN    (OFF_Q     + SZ_MAP)
#define OFF_K     (OFF_QN    + SZ_MAP)
#define OFF_V     (OFF_K     + SZ_KV)
#define OFF_VLOC  (OFF_V     + SZ_KV)
#define OFF_O1    (OFF_VLOC  + SZ_MAP)
#define OFF_O2    (OFF_O1    + SZ_MAP)
#define OFF_S1    (OFF_O2    + SZ_MAP)
#define OFF_A2    (OFF_S1    + SZ_ATTH)
#define OFF_PS    (OFF_A2    + SZ_ATTH)
#define OFF_LI    (OFF_PS    + SZ_PS)
#define SCRATCH_TOTAL (OFF_LI + SZ_LI)

__device__ float g_scratch[SCRATCH_TOTAL];

// ---------------- packed f32x2 helpers ----------------
__device__ __forceinline__ void ffma2(float2& acc, const float2 a, const float2 b) {
    asm("fma.rn.f32x2 %0, %1, %2, %0;"
        : "+l"(reinterpret_cast<unsigned long long&>(acc))
        : "l"(reinterpret_cast<const unsigned long long&>(a)),
          "l"(reinterpret_cast<const unsigned long long&>(b)));
}
__device__ __forceinline__ float2 dup2(float v) {
    float2 r;
    asm("mov.b64 %0, {%1, %1};"
        : "=l"(reinterpret_cast<unsigned long long&>(r)) : "f"(v));
    return r;
}

// =================== unified GEMM: 64m x 64p tile, 128 threads ===================
// Y[b][m][p] = sum_k A[m][k]*X[b][k][p] (+bias), optional hardswish on X.
// thread tile: 4m x 8p.  Requires P % 8 == 0.
__global__ __launch_bounds__(128)
void gemm64(const float* __restrict__ A, const float* __restrict__ X,
            const float* __restrict__ bias, float* __restrict__ Y,
            int M, int K, int P, int hsw)
{
    __shared__ __align__(16) float As[16 * 68];
    __shared__ __align__(16) float Xs[16 * 68];
    int b  = blockIdx.z;
    int m0 = blockIdx.y * 64;
    int p0 = blockIdx.x * 64;
    int t  = threadIdx.x;
    int ty = t >> 3, tx = t & 7;     // ty: 0..15 (m-group), tx: 0..7 (p-group of 8)

    float2 acc[4][4];
#pragma unroll
    for (int i = 0; i < 4; i++)
#pragma unroll
        for (int j = 0; j < 4; j++) acc[i][j] = make_float2(0.f, 0.f);

    for (int k0 = 0; k0 < K; k0 += 16) {
#pragma unroll
        for (int it = 0; it < 8; it++) {
            int idx = t + it * 128;
            int m = idx >> 4, k = idx & 15;
            As[k * 68 + m] = A[(size_t)(m0 + m) * K + k0 + k];
        }
#pragma unroll
        for (int it = 0; it < 2; it++) {
            int u = t + it * 128;
            int kk = u >> 4, pg = u & 15;
            int p = p0 + pg * 4;
            float4 v = make_float4(0.f, 0.f, 0.f, 0.f);
            if (p < P) v = *(const float4*)&X[((size_t)b * K + k0 + kk) * P + p];
            if (hsw) {
                float c;
                c = fminf(fmaxf(v.x + 3.f, 0.f), 6.f); v.x = v.x * c * (1.f / 6.f);
                c = fminf(fmaxf(v.y + 3.f, 0.f), 6.f); v.y = v.y * c * (1.f / 6.f);
                c = fminf(fmaxf(v.z + 3.f, 0.f), 6.f); v.z = v.z * c * (1.f / 6.f);
                c = fminf(fmaxf(v.w + 3.f, 0.f), 6.f); v.w = v.w * c * (1.f / 6.f);
            }
            *(float4*)&Xs[kk * 68 + pg * 4] = v;
        }
        __syncthreads();
#pragma unroll
        for (int kk = 0; kk < 16; kk++) {
            float2 am[4];
#pragma unroll
            for (int i = 0; i < 4; i++) am[i] = dup2(As[kk * 68 + ty * 4 + i]);
            float4 x0 = *(const float4*)&Xs[kk * 68 + tx * 8];
            float4 x1 = *(const float4*)&Xs[kk * 68 + tx * 8 + 4];
            float2 xp[4] = { make_float2(x0.x, x0.y), make_float2(x0.z, x0.w),
                             make_float2(x1.x, x1.y), make_float2(x1.z, x1.w) };
#pragma unroll
            for (int i = 0; i < 4; i++)
#pragma unroll
                for (int j = 0; j < 4; j++) ffma2(acc[i][j], am[i], xp[j]);
        }
        __syncthreads();
    }
    int pbase = p0 + tx * 8;
    if (pbase < P) {
#pragma unroll
        for (int i = 0; i < 4; i++) {
            int m = m0 + ty * 4 + i;
            float bv = bias ? bias[m] : 0.f;
            float* yb = Y + ((size_t)b * M + m) * P + pbase;
            float4 w0 = make_float4(acc[i][0].x + bv, acc[i][0].y + bv,
                                    acc[i][1].x + bv, acc[i][1].y + bv);
            float4 w1 = make_float4(acc[i][2].x + bv, acc[i][2].y + bv,
                                    acc[i][3].x + bv, acc[i][3].y + bv);
            *(float4*)yb = w0;
            *(float4*)(yb + 4) = w1;
        }
    }
}

// =================== 3x3 s2 pad1 conv (implicit GEMM, 64m x 64p, 128 thr) ===================
__global__ __launch_bounds__(128)
void conv3x3_kernel(const float* __restrict__ X, const float* __restrict__ W,
                    const float* __restrict__ bias, float* __restrict__ Y,
                    int CinPG, int CinTot, int CoutPG, int Cout)
{
    __shared__ __align__(16) float As[16 * 68];
    __shared__ __align__(16) float Xs[16 * 68];
    int b  = blockIdx.z;
    int m0 = blockIdx.y * 64;
    int p0 = blockIdx.x * 64;
    int g  = m0 / CoutPG;
    int K  = CinPG * 9;
    int t  = threadIdx.x;
    int ty = t >> 3, tx = t & 7;

    const float* Xb = X + (size_t)(b * CinTot + g * CinPG) * NNF;

    float2 acc[4][4];
#pragma unroll
    for (int i = 0; i < 4; i++)
#pragma unroll
        for (int j = 0; j < 4; j++) acc[i][j] = make_float2(0.f, 0.f);

    for (int k0 = 0; k0 < K; k0 += 16) {
#pragma unroll
        for (int it = 0; it < 8; it++) {
            int idx = t + it * 128;
            int m = idx >> 4, k = idx & 15;
            As[k * 68 + m] = W[(size_t)(m0 + m) * K + k0 + k];
        }
#pragma unroll
        for (int it = 0; it < 8; it++) {
            int u = t + it * 128;
            int kk = u >> 6, pp = u & 63;
            int k = k0 + kk;
            int ci = k / 9, r9 = k - ci * 9;
            int ky = r9 / 3, kx = r9 - ky * 3;
            int p = p0 + pp;
            float v = 0.f;
            if (p < PQ) {
                int py = p / 28, px = p - py * 28;
                int iy = 2 * py - 1 + ky, ix = 2 * px - 1 + kx;
                if ((unsigned)iy < (unsigned)HIN && (unsigned)ix < (unsigned)HIN)
                    v = Xb[(size_t)ci * NNF + iy * HIN + ix];
            }
            Xs[kk * 68 + pp] = v;
        }
        __syncthreads();
#pragma unroll
        for (int kk = 0; kk < 16; kk++) {
            float2 am[4];
#pragma unroll
            for (int i = 0; i < 4; i++) am[i] = dup2(As[kk * 68 + ty * 4 + i]);
            float4 x0 = *(const float4*)&Xs[kk * 68 + tx * 8];
            float4 x1 = *(const float4*)&Xs[kk * 68 + tx * 8 + 4];
            float2 xp[4] = { make_float2(x0.x, x0.y), make_float2(x0.z, x0.w),
                             make_float2(x1.x, x1.y), make_float2(x1.z, x1.w) };
#pragma unroll
            for (int i = 0; i < 4; i++)
#pragma unroll
                for (int j = 0; j < 4; j++) ffma2(acc[i][j], am[i], xp[j]);
        }
        __syncthreads();
    }
    int pbase = p0 + tx * 8;
    if (pbase < PQ) {
#pragma unroll
        for (int i = 0; i < 4; i++) {
            int m = m0 + ty * 4 + i;
            float bv = bias ? bias[m] : 0.f;
            float* yb = Y + ((size_t)b * Cout + m) * PQ + pbase;
            float4 w0 = make_float4(acc[i][0].x + bv, acc[i][0].y + bv,
                                    acc[i][1].x + bv, acc[i][1].y + bv);
            float4 w1 = make_float4(acc[i][2].x + bv, acc[i][2].y + bv,
                                    acc[i][3].x + bv, acc[i][3].y + bv);
            *(float4*)yb = w0;
            *(float4*)(yb + 4) = w1;
        }
    }
}

// ---------------- GroupNorm ----------------
__global__ __launch_bounds__(256)
void gn_kernel(float* __restrict__ data, const float* __restrict__ w,
               const float* __restrict__ bgn, int HW,
               const float* __restrict__ addsrc, float* __restrict__ dst)
{
    __shared__ float rs[256], rss[256];
    __shared__ float sstat[2];
    int grp = blockIdx.x, b = blockIdx.y;
    int t = threadIdx.x;
    size_t base = ((size_t)b * CDIM + grp * 16) * HW;
    int n = 16 * HW;
    float s = 0.f, ss = 0.f;
    for (int e = t; e < n; e += 256) {
        float v = data[base + e];
        s += v; ss += v * v;
    }
    rs[t] = s; rss[t] = ss;
    __syncthreads();
    for (int o = 128; o > 0; o >>= 1) {
        if (t < o) { rs[t] += rs[t + o]; rss[t] += rss[t + o]; }
        __syncthreads();
    }
    if (t == 0) {
        float mean = rs[0] / (float)n;
        float var  = rss[0] / (float)n - mean * mean;
        sstat[0] = mean;
        sstat[1] = rsqrtf(var + 1e-5f);
    }
    __syncthreads();
    float mean = sstat[0], rstd = sstat[1];
    float* out = dst ? dst : data;
    for (int e = t; e < n; e += 256) {
        int c = grp * 16 + e / HW;
        float v = (data[base + e] - mean) * rstd * w[c] + bgn[c];
        if (addsrc) v += addsrc[base + e];
        out[base + e] = v;
    }
}

// ---------------- depthwise 3x3 s2 conv + bias + stride-2 pool add ----------------
__global__ __launch_bounds__(256)
void dwpool_kernel(const float* __restrict__ x, const float* __restrict__ w,
                   const float* __restrict__ bias, float* __restrict__ tq)
{
    int idx = blockIdx.x * 256 + threadIdx.x;
    if (idx >= NB * CIN * PQ) return;
    int p = idx % PQ;
    int c = (idx / PQ) % CIN;
    int b = idx / (PQ * CIN);
    int py = p / 28, px = p - py * 28;
    const float* xb = x + ((size_t)b * CIN + c) * NNF;
    float acc = bias[c] + xb[(2 * py) * HIN + 2 * px];
#pragma unroll
    for (int ky = 0; ky < 3; ky++) {
        int iy = 2 * py - 1 + ky;
        if ((unsigned)iy >= (unsigned)HIN) continue;
#pragma unroll
        for (int kx = 0; kx < 3; kx++) {
            int ix = 2 * px - 1 + kx;
            if ((unsigned)ix >= (unsigned)HIN) continue;
            acc += w[c * 9 + ky * 3 + kx] * xb[iy * HIN + ix];
        }
    }
    tq[idx] = acc;
}

// ---------------- head-axis l2 norm for K (in place) ----------------
__global__ __launch_bounds__(256)
void hn_k_kernel(float* __restrict__ k)
{
    int idx = blockIdx.x * 256 + threadIdx.x;
    if (idx >= NB * HD * NNF) return;
    int nidx = idx % NNF;
    int d = (idx / NNF) % HD;
    int b = idx / (NNF * HD);
    float v[NHEADS];
    float s = 0.f;
#pragma unroll
    for (int h = 0; h < NHEADS; h++) {
        v[h] = k[((size_t)b * CDIM + h * HD + d) * NNF + nidx];
        s += v[h] * v[h];
    }
    float inv = 1.f / fmaxf(sqrtf(s), 1e-12f);
#pragma unroll
    for (int h = 0; h < NHEADS; h++)
        k[((size_t)b * CDIM + h * HD + d) * NNF + nidx] = v[h] * inv;
}

// ---------------- head-axis l2 norm for Q + transpose to [b][p][c] ----------------
__global__ __launch_bounds__(256)
void hn_q_kernel(const float* __restrict__ q, float* __restrict__ qn)
{
    int idx = blockIdx.x * 256 + threadIdx.x;
    if (idx >= NB * HD * PQ) return;
    int p = idx % PQ;
    int d = (idx / PQ) % HD;
    int b = idx / (PQ * HD);
    float v[NHEADS];
    float s = 0.f;
#pragma unroll
    for (int h = 0; h < NHEADS; h++) {
        v[h] = q[((size_t)b * CDIM + h * HD + d) * PQ + p];
        s += v[h] * v[h];
    }
    float inv = 1.f / fmaxf(sqrtf(s), 1e-12f);
#pragma unroll
    for (int h = 0; h < NHEADS; h++)
        qn[((size_t)b * PQ + p) * CDIM + h * HD + d] = v[h] * inv;
}

// =================== attention: exp(th1-mixed scores) -> bf16 + partial sums ===================
// block: 32q x 64n tile, 128 threads, thread-tile 4q x 4n.
__global__ __launch_bounds__(128)
void attn_s1_kernel(const float* __restrict__ qn, const float* __restrict__ kn,
                    const float* __restrict__ th1, const float* __restrict__ ab,
                    const int* __restrict__ bidx, __nv_bfloat16* __restrict__ s1,
                    float* __restrict__ partial)
{
    __shared__ __align__(16) float qs[32 * 68];
    __shared__ __align__(16) float ks[64 * 68];
    __shared__ float2 th1s[64];
    int b  = blockIdx.z;
    int q0 = blockIdx.y * 32;
    int n0 = blockIdx.x * 64;
    int t  = threadIdx.x;
    int qy = t >> 4, tx = t & 15;

    if (t < 64) { float w = th1[t]; th1s[t] = make_float2(w, w); }

    int4 bi[4];
#pragma unroll
    for (int j = 0; j < 4; j++) {
        int q = q0 + qy * 4 + j;
        bi[j] = (q < PQ) ? *(const int4*)&bidx[(size_t)q * NNF + n0 + tx * 4]
                         : make_int4(0, 0, 0, 0);
    }

    float2 acc[NHEADS][4][2];
#pragma unroll
    for (int o = 0; o < NHEADS; o++)
#pragma unroll
        for (int j = 0; j < 4; j++) {
            acc[o][j][0] = make_float2(0.f, 0.f);
            acc[o][j][1] = make_float2(0.f, 0.f);
        }

    for (int i = 0; i < NHEADS; i++) {
        __syncthreads();
#pragma unroll
        for (int it = 0; it < 4; it++) {
            int u = t + it * 128;
            int qq = u >> 4, dg = u & 15;
            int q = q0 + qq;
            float4 v = make_float4(0.f, 0.f, 0.f, 0.f);
            if (q < PQ) v = *(const float4*)&qn[((size_t)b * PQ + q) * CDIM + i * HD + dg * 4];
            *(float4*)&qs[qq * 68 + dg * 4] = v;
        }
#pragma unroll
        for (int it = 0; it < 8; it++) {
            int u = t + it * 128;
            int dd = u >> 4, ng = u & 15;
            float4 v = *(const float4*)&kn[((size_t)b * CDIM + i * HD + dd) * NNF + n0 + ng * 4];
            *(float4*)&ks[dd * 68 + ng * 4] = v;
        }
        __syncthreads();

        float2 s[4][2];
#pragma unroll
        for (int j = 0; j < 4; j++) { s[j][0] = make_float2(0.f, 0.f); s[j][1] = make_float2(0.f, 0.f); }

#pragma unroll 8
        for (int d = 0; d < HD; d++) {
            float4 k4 = *(const float4*)&ks[d * 68 + tx * 4];
            float2 k01 = make_float2(k4.x, k4.y);
            float2 k23 = make_float2(k4.z, k4.w);
#pragma unroll
            for (int j = 0; j < 4; j++) {
                float2 qp = dup2(qs[(qy * 4 + j) * 68 + d]);
                ffma2(s[j][0], qp, k01);
                ffma2(s[j][1], qp, k23);
            }
        }
        const float* abr = ab + (size_t)i * NNF;
        float2 w[NHEADS];
#pragma unroll
        for (int o = 0; o < NHEADS; o++) w[o] = th1s[o * 8 + i];
#pragma unroll
        for (int j = 0; j < 4; j++) {
            float2 t01 = make_float2(s[j][0].x * SCALE + abr[bi[j].x],
                                     s[j][0].y * SCALE + abr[bi[j].y]);
            float2 t23 = make_float2(s[j][1].x * SCALE + abr[bi[j].z],
                                     s[j][1].y * SCALE + abr[bi[j].w]);
#pragma unroll
            for (int o = 0; o < NHEADS; o++) {
                ffma2(acc[o][j][0], w[o], t01);
                ffma2(acc[o][j][1], w[o], t23);
            }
        }
    }

#pragma unroll
    for (int o = 0; o < NHEADS; o++) {
#pragma unroll
        for (int j = 0; j < 4; j++) {
            int q = q0 + qy * 4 + j;
            float4 ev;
            ev.x = __expf(acc[o][j][0].x);
            ev.y = __expf(acc[o][j][0].y);
            ev.z = __expf(acc[o][j][1].x);
            ev.w = __expf(acc[o][j][1].y);
            float ps = (ev.x + ev.y) + (ev.z + ev.w);
#pragma unroll
            for (int off = 8; off > 0; off >>= 1)
                ps += __shfl_xor_sync(0xffffffffu, ps, off);
            if (q < PQ) {
                __nv_bfloat162 e01 = __floats2bfloat162_rn(ev.x, ev.y);
                __nv_bfloat162 e23 = __floats2bfloat162_rn(ev.z, ev.w);
                uint2 pk;
                pk.x = *(unsigned*)&e01;
                pk.y = *(unsigned*)&e23;
                *(uint2*)&s1[(((size_t)b * NHEADS + o) * PQ + q) * NNF + n0 + tx * 4] = pk;
                if (tx == 0)
                    partial[(((size_t)b * PQ + q) * NHEADS + o) * NTILES + blockIdx.x] = ps;
            }
        }
    }
}

// ---------------- reduce partial sums -> 1/l ----------------
__global__ __launch_bounds__(256)
void reduce_l_kernel(const float* __restrict__ partial, float* __restrict__ linv)
{
    int idx = blockIdx.x * 256 + threadIdx.x;
    if (idx >= NB * PQ * NHEADS) return;
    const float* p = partial + (size_t)idx * NTILES;
    float s = 0.f;
#pragma unroll
    for (int i = 0; i < NTILES; i++) s += p[i];
    linv[idx] = 1.f / s;
}

// ---------------- normalize + th2 head-mix (bf16 streaming) ----------------
__global__ __launch_bounds__(256)
void mix_kernel(const __nv_bfloat16* __restrict__ e, const float* __restrict__ linv,
                const float* __restrict__ th2, __nv_bfloat16* __restrict__ a2)
{
    __shared__ float th2s[64];
    int q = blockIdx.x, b = blockIdx.y, t = threadIdx.x;
    if (t < 64) th2s[t] = th2[t];
    __syncthreads();
    float li[NHEADS];
#pragma unroll
    for (int o = 0; o < NHEADS; o++)
        li[o] = linv[((size_t)b * PQ + q) * NHEADS + o];
    size_t base = ((size_t)b * NHEADS * PQ + q) * NNF;
    for (int n = t * 8; n < NNF; n += 2048) {
        float p[NHEADS][8];
#pragma unroll
        for (int i = 0; i < NHEADS; i++) {
            uint4 raw = *(const uint4*)&e[base + (size_t)i * PQ * NNF + n];
            const __nv_bfloat162* h = (const __nv_bfloat162*)&raw;
#pragma unroll
            for (int g = 0; g < 4; g++) {
                float2 f = __bfloat1622float2(h[g]);
                p[i][g * 2 + 0] = f.x * li[i];
                p[i][g * 2 + 1] = f.y * li[i];
            }
        }
#pragma unroll
        for (int o = 0; o < NHEADS; o++) {
            float s[8];
#pragma unroll
            for (int g = 0; g < 8; g++) s[g] = 0.f;
#pragma unroll
            for (int i = 0; i < NHEADS; i++) {
                float w = th2s[o * 8 + i];
#pragma unroll
                for (int g = 0; g < 8; g++) s[g] += w * p[i][g];
            }
            uint4 outp;
            __nv_bfloat162* oh = (__nv_bfloat162*)&outp;
#pragma unroll
            for (int g = 0; g < 4; g++)
                oh[g] = __floats2bfloat162_rn(s[g * 2], s[g * 2 + 1]);
            *(uint4*)&a2[base + (size_t)o * PQ * NNF + n] = outp;
        }
    }
}

// =================== AV GEMM (64d x 64q tile, 128 thr) + v_local add ===================
__global__ __launch_bounds__(128)
void av_kernel(const __nv_bfloat16* __restrict__ a2, const float* __restrict__ v,
               const float* __restrict__ vloc, float* __restrict__ out)
{
    __shared__ __align__(16) float As[16 * 68];
    __shared__ __align__(16) float Xs[16 * 68];
    int b = blockIdx.z, o = blockIdx.y, p0 = blockIdx.x * 64;
    int t = threadIdx.x, ty = t >> 3, tx = t & 7;
    const float* vb = v + ((size_t)b * CDIM + o * HD) * NNF;
    const __nv_bfloat16* ab = a2 + (((size_t)b * NHEADS + o) * PQ) * NNF;

    float2 acc[4][4];
#pragma unroll
    for (int i = 0; i < 4; i++)
#pragma unroll
        for (int j = 0; j < 4; j++) acc[i][j] = make_float2(0.f, 0.f);

    for (int n0 = 0; n0 < NNF; n0 += 16) {
#pragma unroll
        for (int it = 0; it < 8; it++) {
            int idx = t + it * 128;
            int dd = idx >> 4, kk = idx & 15;
            As[kk * 68 + dd] = vb[(size_t)dd * NNF + n0 + kk];
        }
#pragma unroll
        for (int it = 0; it < 8; it++) {
            int idx = t + it * 128;
            int pp = idx >> 4, kk = idx & 15;
            int p = p0 + pp;
            Xs[kk * 68 + pp] = (p < PQ) ? __bfloat162float(ab[(size_t)p * NNF + n0 + kk]) : 0.f;
        }
        __syncthreads();
#pragma unroll
        for (int kk = 0; kk < 16; kk++) {
            float2 am[4];
#pragma unroll
            for (int i = 0; i < 4; i++) am[i] = dup2(As[kk * 68 + ty * 4 + i]);
            float4 x0 = *(const float4*)&Xs[kk * 68 + tx * 8];
            float4 x1 = *(const float4*)&Xs[kk * 68 + tx * 8 + 4];
            float2 xp[4] = { make_float2(x0.x, x0.y), make_float2(x0.z, x0.w),
                             make_float2(x1.x, x1.y), make_float2(x1.z, x1.w) };
#pragma unroll
            for (int i = 0; i < 4; i++)
#pragma unroll
                for (int j = 0; j < 4; j++) ffma2(acc[i][j], am[i], xp[j]);
        }
        __syncthreads();
    }
    int pbase = p0 + tx * 8;
    if (pbase < PQ) {
#pragma unroll
        for (int i = 0; i < 4; i++) {
            int c = o * HD + ty * 4 + i;
            const float* vl = vloc + ((size_t)b * CDIM + c) * PQ + pbase;
            float* ob = out + ((size_t)b * CDIM + c) * PQ + pbase;
            float4 w0 = make_float4(acc[i][0].x + vl[0], acc[i][0].y + vl[1],
                                    acc[i][1].x + vl[2], acc[i][1].y + vl[3]);
            float4 w1 = make_float4(acc[i][2].x + vl[4], acc[i][2].y + vl[5],
                                    acc[i][3].x + vl[6], acc[i][3].y + vl[7]);
            *(float4*)ob = w0;
            *(float4*)(ob + 4) = w1;
        }
    }
}

// ---------------- launch ----------------
extern "C" void kernel_launch(void* const* d_in, const int* in_sizes, int n_in,
                              void* d_out, int out_size)
{
    const float* x         = (const float*)d_in[0];
    const float* q_local_w = (const float*)d_in[1];
    const float* q_local_b = (const float*)d_in[2];
    const float* q_proj_w  = (const float*)d_in[3];
    const float* q_proj_b  = (const float*)d_in[4];
    const float* q_gn_w    = (const float*)d_in[5];
    const float* q_gn_b    = (const float*)d_in[6];
    const float* k_w       = (const float*)d_in[7];
    const float* k_gn_w    = (const float*)d_in[8];
    const float* k_gn_b    = (const float*)d_in[9];
    const float* v_w       = (const float*)d_in[10];
    const float* v_gn_w    = (const float*)d_in[11];
    const float* v_gn_b    = (const float*)d_in[12];
    const float* loc_w     = (const float*)d_in[13];
    const float* loc_b     = (const float*)d_in[14];
    const float* loc_gn_w  = (const float*)d_in[15];
    const float* loc_gn_b  = (const float*)d_in[16];
    const float* th1_w     = (const float*)d_in[17];
    const float* th2_w     = (const float*)d_in[18];
    const float* out_w     = (const float*)d_in[19];
    const float* out_gn_w  = (const float*)d_in[20];
    const float* out_gn_b  = (const float*)d_in[21];
    const float* proj_w    = (const float*)d_in[22];
    const float* proj_b    = (const float*)d_in[23];
    const float* proj_gn_w = (const float*)d_in[24];
    const float* proj_gn_b = (const float*)d_in[25];
    const float* attn_bias = (const float*)d_in[26];
    const int*   bias_idxs = (const int*)d_in[27];
    float* out = (float*)d_out;

    float* S = nullptr;
    cudaGetSymbolAddress((void**)&S, g_scratch);
    float* xproj = S + OFF_XPROJ;
    float* tq    = S + OFF_TQ;
    float* qbuf  = S + OFF_Q;
    float* qn    = S + OFF_QN;
    float* kbuf  = S + OFF_K;
    float* vbuf  = S + OFF_V;
    float* vloc  = S + OFF_VLOC;
    float* o1    = S + OFF_O1;
    float* o2    = S + OFF_O2;
    __nv_bfloat16* s1 = (__nv_bfloat16*)(S + OFF_S1);
    __nv_bfloat16* a2 = (__nv_bfloat16*)(S + OFF_A2);
    float* psum  = S + OFF_PS;
    float* linv  = S + OFF_LI;

    dim3 blk128(128);
    dim3 blk256(256);

    // proj path: conv3x3 s2 (256->512) + bias, then GN in place
    conv3x3_kernel<<<dim3(13, 8, NB), blk128>>>(x, proj_w, proj_b, xproj, 256, 256, 512, 512);
    gn_kernel<<<dim3(32, NB), blk256>>>(xproj, proj_gn_w, proj_gn_b, PQ, nullptr, nullptr);

    // q path
    dwpool_kernel<<<dim3((NB * CIN * PQ + 255) / 256), blk256>>>(x, q_local_w, q_local_b, tq);
    gemm64<<<dim3(13, 8, NB), blk128>>>(q_proj_w, tq, q_proj_b, qbuf, 512, 256, PQ, 0);
    gn_kernel<<<dim3(32, NB), blk256>>>(qbuf, q_gn_w, q_gn_b, PQ, nullptr, nullptr);

    // k path
    gemm64<<<dim3(49, 8, NB), blk128>>>(k_w, x, nullptr, kbuf, 512, 256, NNF, 0);
    gn_kernel<<<dim3(32, NB), blk256>>>(kbuf, k_gn_w, k_gn_b, NNF, nullptr, nullptr);
    hn_k_kernel<<<dim3((NB * HD * NNF + 255) / 256), blk256>>>(kbuf);

    // v path
    gemm64<<<dim3(49, 8, NB), blk128>>>(v_w, x, nullptr, vbuf, 512, 256, NNF, 0);
    gn_kernel<<<dim3(32, NB), blk256>>>(vbuf, v_gn_w, v_gn_b, NNF, nullptr, nullptr);

    // v_local: grouped conv3x3 s2 (8 groups of 64) + bias, GN in place
    conv3x3_kernel<<<dim3(13, 8, NB), blk128>>>(vbuf, loc_w, loc_b, vloc, 64, 512, 64, 512);
    gn_kernel<<<dim3(32, NB), blk256>>>(vloc, loc_gn_w, loc_gn_b, PQ, nullptr, nullptr);

    // q l2norm over heads + transpose
    hn_q_kernel<<<dim3((NB * HD * PQ + 255) / 256), blk256>>>(qbuf, qn);

    // attention: exp(QK*scale + bias mixed by th1) -> bf16, partial row sums
    attn_s1_kernel<<<dim3(NTILES, 25, NB), blk128>>>(qn, kbuf, th1_w, attn_bias,
                                                     bias_idxs, s1, psum);

    // row sums -> 1/l
    reduce_l_kernel<<<dim3((NB * PQ * NHEADS + 255) / 256), blk256>>>(psum, linv);

    // normalize + th2 mix (bf16 -> bf16)
    mix_kernel<<<dim3(PQ, NB), blk256>>>(s1, linv, th2_w, a2);

    // AV + v_local
    av_kernel<<<dim3(13, NHEADS, NB), blk128>>>(a2, vbuf, vloc, o1);

    // hardswish -> out 1x1 conv (512->512)
    gemm64<<<dim3(13, 8, NB), blk128>>>(out_w, o1, nullptr, o2, 512, 512, PQ, 1);

    // final GN + residual add -> d_out
    gn_kernel<<<dim3(32, NB), blk256>>>(o2, out_gn_w, out_gn_b, PQ, xproj, out);
}